// round 8
// baseline (speedup 1.0000x reference)
#include <cuda_runtime.h>
#include <cstddef>

#define Bb 8
#define Tt 2048
#define Dd 512
#define Hh 512
#define FOURH 2048
#define GRID_R 128

typedef unsigned long long u64;

// ---------------- scratch (static device globals: allocation-free) ----------------
__device__ float g_wx[(size_t)Bb * Tt * FOURH];   // 128 MiB: precomputed x @ W^T + b
__device__ float g_h[2][Bb * Hh];                 // double-buffered hidden state
__device__ unsigned g_cnt[16 * 32];               // 16 per-warp-slot counters, 128B apart

// ---------------- packed f32x2 helpers (b64 regs via "l" constraint) ----------------
__device__ __forceinline__ void fma2(u64 &acc, u64 a, u64 b) {
    asm("fma.rn.f32x2 %0, %1, %2, %0;" : "+l"(acc) : "l"(a), "l"(b));
}
__device__ __forceinline__ u64 dup2(float s) {
    u64 d; asm("mov.b64 %0, {%1, %1};" : "=l"(d) : "f"(s)); return d;
}
__device__ __forceinline__ void unpack2(u64 v, float &lo, float &hi) {
    asm("mov.b64 {%0, %1}, %2;" : "=f"(lo), "=f"(hi) : "l"(v));
}

// ---------------- scoped sync primitives ----------------
__device__ __forceinline__ void cnt_arrive_release(unsigned* p) {
    asm volatile("red.release.gpu.global.add.u32 [%0], %1;"
                 :: "l"(p), "r"(1u) : "memory");
}
__device__ __forceinline__ unsigned ld_acquire(const unsigned* p) {
    unsigned v;
    asm volatile("ld.acquire.gpu.global.u32 %0, [%1];"
                 : "=r"(v) : "l"(p) : "memory");
    return v;
}

// ---------------- fast gate math (MUFU-based, ~1e-7 rel err) ----------------
__device__ __forceinline__ float sigm_f(float x) {
    return __fdividef(1.f, 1.f + __expf(-x));
}
__device__ __forceinline__ float tanh_f(float x) {
    float e = __expf(2.f * x);
    return 1.f - __fdividef(2.f, e + 1.f);
}

// =====================================================================
// Kernel 1: Wx = x[16384,512] @ W_w[2048,512]^T + W_b  -> g_wx[16384,2048]
// (unchanged; ~60% of fp32x2 roofline)
// =====================================================================
__global__ void __launch_bounds__(256) gemm_wx_kernel(
    const float* __restrict__ x, const float* __restrict__ Ww,
    const float* __restrict__ Wb)
{
    __shared__ __align__(16) float a_s[32][132];
    __shared__ __align__(16) float b_s[32][132];

    const int tid = threadIdx.x;
    const int tx = tid & 15, ty = tid >> 4;
    const int m0 = blockIdx.y * 128, n0 = blockIdx.x * 128;

    u64 acc[8][4];
    #pragma unroll
    for (int i = 0; i < 8; i++)
        #pragma unroll
        for (int j = 0; j < 4; j++) acc[i][j] = 0ull;

    const int lr = tid >> 3;
    const int kq = (tid & 7) * 4;

    for (int kc = 0; kc < 512; kc += 32) {
        __syncthreads();
        #pragma unroll
        for (int i = 0; i < 4; i++) {
            int r = lr + 32 * i;
            float4 av = *(const float4*)&x[(size_t)(m0 + r) * 512 + kc + kq];
            a_s[kq + 0][r] = av.x; a_s[kq + 1][r] = av.y;
            a_s[kq + 2][r] = av.z; a_s[kq + 3][r] = av.w;
            float4 bv = *(const float4*)&Ww[(size_t)(n0 + r) * 512 + kc + kq];
            b_s[kq + 0][r] = bv.x; b_s[kq + 1][r] = bv.y;
            b_s[kq + 2][r] = bv.z; b_s[kq + 3][r] = bv.w;
        }
        __syncthreads();
        #pragma unroll
        for (int k = 0; k < 32; k++) {
            float4 af0 = *(const float4*)&a_s[k][ty * 8];
            float4 af1 = *(const float4*)&a_s[k][ty * 8 + 4];
            ulonglong2 b01 = *(const ulonglong2*)&b_s[k][tx * 8];
            ulonglong2 b23 = *(const ulonglong2*)&b_s[k][tx * 8 + 4];
            u64 ad[8];
            ad[0] = dup2(af0.x); ad[1] = dup2(af0.y); ad[2] = dup2(af0.z); ad[3] = dup2(af0.w);
            ad[4] = dup2(af1.x); ad[5] = dup2(af1.y); ad[6] = dup2(af1.z); ad[7] = dup2(af1.w);
            #pragma unroll
            for (int i = 0; i < 8; i++) {
                fma2(acc[i][0], ad[i], b01.x);
                fma2(acc[i][1], ad[i], b01.y);
                fma2(acc[i][2], ad[i], b23.x);
                fma2(acc[i][3], ad[i], b23.y);
            }
        }
    }

    float wb[8];
    #pragma unroll
    for (int j = 0; j < 8; j++) wb[j] = Wb[n0 + tx * 8 + j];

    #pragma unroll
    for (int i = 0; i < 8; i++) {
        float o[8];
        #pragma unroll
        for (int jp = 0; jp < 4; jp++) {
            float lo, hi; unpack2(acc[i][jp], lo, hi);
            o[jp * 2]     = lo + wb[jp * 2];
            o[jp * 2 + 1] = hi + wb[jp * 2 + 1];
        }
        size_t row = (size_t)(m0 + ty * 8 + i);
        float4* dst = (float4*)&g_wx[row * FOURH + n0 + tx * 8];
        dst[0] = make_float4(o[0], o[1], o[2], o[3]);
        dst[1] = make_float4(o[4], o[5], o[6], o[7]);
    }
}

// =====================================================================
// Kernel 2: persistent recurrent sLSTM. 128 blocks x 512 threads (16 warps).
// Block owns hidden units [4*blk, 4*blk+4).
// Warp w: unit ju = w>>2, batch-pair bp = w&3; computes ALL 4 gates for
// (unit, 2 batches) from smem-staged h, finalizes and publishes itself,
// then arrives on its own per-warp-slot counter (no trailing block sync).
// =====================================================================
__global__ void __launch_bounds__(512) lstm_rec_kernel(
    const float* __restrict__ Uw, const float* __restrict__ Ub,
    const float* __restrict__ alpha, float* __restrict__ out)
{
    __shared__ __align__(16) float h_s[Bb][Hh];   // 16 KB staged hidden state

    const int tid  = threadIdx.x;
    const int w    = tid >> 5;
    const int lane = tid & 31;
    const int ju   = w >> 2;       // local hidden unit 0..3
    const int bp   = w & 3;        // batch pair (batches 2bp, 2bp+1)
    const int blk  = blockIdx.x;
    const int jg   = blk * 4 + ju; // global hidden unit for this warp

    // lane's (gate, batch) slot: m = (lane>>2)&7, g = m&3, bi = m>>2
    const int m  = (lane >> 2) & 7;
    const int g  = m & 3;
    const int bi = m >> 2;
    const int b  = 2 * bp + bi;    // batch 0..7 for this lane's slot

    // U_w register-resident: rows (g, jg) for g=0..3; lane owns cols 4*lane+128*q
    ulonglong2 u[4][4];
    #pragma unroll
    for (int gg = 0; gg < 4; gg++)
        #pragma unroll
        for (int q = 0; q < 4; q++)
            u[gg][q] = *(const ulonglong2*)&Uw[(size_t)(gg * Hh + jg) * Hh + 128 * q + 4 * lane];

    const float ub_r    = Ub[g * Hh + jg];
    const float alpha_r = alpha[jg];
    float c_st = 0.f;              // live in lanes 0 and 16 only

    // publish h0 = 0; every warp arrives on its own slot counter
    // (syncthreads -> lane0 release gives transitive visibility of warp0's zeros)
    if (w == 0) g_h[0][blk * 32 + lane] = 0.f;
    __syncthreads();
    if (lane == 0) cnt_arrive_release(&g_cnt[w * 32]);

    for (int t = 0; t < Tt; ++t) {
        // prefetch Wx_t for this lane's (g, b) slot (independent of h; L2-only)
        const float wx = __ldcg(&g_wx[((size_t)b * Tt + t) * FOURH + g * Hh + jg]);

        // ---- barrier: all 16 slot counters reached 128*(t+1) (warp 0 polls)
        if (w == 0) {
            const unsigned tgt = 128u * (unsigned)(t + 1);
            int spins = 0;
            for (;;) {
                unsigned cv = (lane < 16) ? ld_acquire(&g_cnt[lane * 32]) : tgt;
                if (__all_sync(0xffffffffu, cv >= tgt)) break;
                if (++spins > 64) __nanosleep(64);
            }
        }
        __syncthreads();

        // ---- stage h_t into smem (L2-only loads; 2 float4 per thread)
        {
            const float4* src = (const float4*)g_h[t & 1];
            float4* dst = (float4*)&h_s[0][0];
            dst[tid]       = __ldcg(&src[tid]);
            dst[tid + 512] = __ldcg(&src[tid + 512]);
        }
        __syncthreads();

        // ---- dots: 4 gates x 2 batches over full 512 cols (from smem)
        u64 acc[4][2];
        #pragma unroll
        for (int gg = 0; gg < 4; gg++) { acc[gg][0] = 0ull; acc[gg][1] = 0ull; }
        #pragma unroll
        for (int bb2 = 0; bb2 < 2; bb2++) {
            ulonglong2 h2[4];
            #pragma unroll
            for (int q = 0; q < 4; q++)
                h2[q] = *(const ulonglong2*)&h_s[2 * bp + bb2][128 * q + 4 * lane];
            #pragma unroll
            for (int q = 0; q < 4; q++)
                #pragma unroll
                for (int gg = 0; gg < 4; gg++) {
                    fma2(acc[gg][bb2], u[gg][q].x, h2[q].x);
                    fma2(acc[gg][bb2], u[gg][q].y, h2[q].y);
                }
        }

        // collapse pair halves -> v[mm], mm = gate + 4*batchhalf
        float v[8];
        #pragma unroll
        for (int gg = 0; gg < 4; gg++)
            #pragma unroll
            for (int bb2 = 0; bb2 < 2; bb2++) {
                float lo, hi; unpack2(acc[gg][bb2], lo, hi);
                v[gg + 4 * bb2] = lo + hi;
            }

        // 9-shfl butterfly: lane L ends with total for mm=(L>>2)&7
        {
            const bool up16 = (lane & 16) != 0;
            #pragma unroll
            for (int i = 0; i < 4; i++) {
                float a = v[i], bv = v[i + 4];
                float mine = up16 ? bv : a, oth = up16 ? a : bv;
                v[i] = mine + __shfl_xor_sync(0xffffffffu, oth, 16);
            }
            const bool up8 = (lane & 8) != 0;
            #pragma unroll
            for (int i = 0; i < 2; i++) {
                float a = v[i], bv = v[i + 2];
                float mine = up8 ? bv : a, oth = up8 ? a : bv;
                v[i] = mine + __shfl_xor_sync(0xffffffffu, oth, 8);
            }
            const bool up4 = (lane & 4) != 0;
            {
                float a = v[0], bv = v[1];
                float mine = up4 ? bv : a, oth = up4 ? a : bv;
                v[0] = mine + __shfl_xor_sync(0xffffffffu, oth, 4);
            }
            v[0] += __shfl_xor_sync(0xffffffffu, v[0], 2);
            v[0] += __shfl_xor_sync(0xffffffffu, v[0], 1);
        }

        // parallel activations, then gather i/f/o/g at lanes 0 (bi=0), 16 (bi=1)
        const float z = v[0] + wx + ub_r;
        const float a = (g == 3) ? tanh_f(z) : sigm_f(z);
        const float a_f = __shfl_down_sync(0xffffffffu, a, 4);
        const float a_o = __shfl_down_sync(0xffffffffu, a, 8);
        const float a_g = __shfl_down_sync(0xffffffffu, a, 12);

        float hv = 0.f;
        if ((lane & 15) == 0) {
            c_st = alpha_r * (a_f * c_st + a * a_g);
            hv = a_o * tanh_f(c_st);
            g_h[(t + 1) & 1][b * Hh + jg] = hv;
        }
        // warp-scope ordering: lane16's store is released by lane0's RED
        __syncwarp();
        if (lane == 0) cnt_arrive_release(&g_cnt[w * 32]);

        // off-critical-path stores (kernel-end fence covers visibility)
        if ((lane & 15) == 0) {
            out[((size_t)b * Tt + t) * Hh + jg] = hv;
            if (t == Tt - 1) {
                out[(size_t)Bb * Tt * Hh + b * Hh + jg] = hv;                       // final h
                out[(size_t)Bb * Tt * Hh + (size_t)Bb * Hh + b * Hh + jg] = c_st;   // final c
            }
        }
    }

    // block 0 resets counters once every arrival landed (graph-replay safe)
    if (blk == 0 && w == 0 && lane < 16) {
        const unsigned fin = 128u * (unsigned)(Tt + 1);
        int spins = 0;
        while (ld_acquire(&g_cnt[lane * 32]) < fin) {
            if (++spins > 64) __nanosleep(128);
        }
        g_cnt[lane * 32] = 0u;
    }
}

// =====================================================================
extern "C" void kernel_launch(void* const* d_in, const int* in_sizes, int n_in,
                              void* d_out, int out_size)
{
    const float* x     = (const float*)d_in[0];
    const float* Ww    = (const float*)d_in[1];
    const float* Wb    = (const float*)d_in[2];
    const float* Uw    = (const float*)d_in[3];
    const float* Ub    = (const float*)d_in[4];
    const float* alpha = (const float*)d_in[5];
    float* out = (float*)d_out;

    dim3 ggrid(FOURH / 128, (Bb * Tt) / 128);   // 16 x 128
    gemm_wx_kernel<<<ggrid, 256>>>(x, Ww, Wb);
    lstm_rec_kernel<<<GRID_R, 512>>>(Uw, Ub, alpha, out);
}

// round 9
// speedup vs baseline: 1.1560x; 1.1560x over previous
#include <cuda_runtime.h>
#include <cstddef>

#define Bb 8
#define Tt 2048
#define Dd 512
#define Hh 512
#define FOURH 2048
#define GRID_R 128

typedef unsigned long long u64;

// ---------------- scratch (static device globals: allocation-free) ----------------
__device__ float g_wx[(size_t)Bb * Tt * FOURH];   // 128 MiB: precomputed x @ W^T + b
__device__ float g_h[2][Bb * Hh];                 // double-buffered hidden state
__device__ unsigned g_bar;                        // monotonic grid barrier counter (self-resetting)

// ---------------- packed f32x2 helpers (b64 regs via "l" constraint) ----------------
__device__ __forceinline__ void fma2(u64 &acc, u64 a, u64 b) {
    asm("fma.rn.f32x2 %0, %1, %2, %0;" : "+l"(acc) : "l"(a), "l"(b));
}
__device__ __forceinline__ void unpack2(u64 v, float &lo, float &hi) {
    asm("mov.b64 {%0, %1}, %2;" : "=f"(lo), "=f"(hi) : "l"(v));
}

// ---------------- scoped sync primitives ----------------
__device__ __forceinline__ void bar_arrive_release() {
    asm volatile("red.release.gpu.global.add.u32 [%0], %1;"
                 :: "l"(&g_bar), "r"(1u) : "memory");
}
__device__ __forceinline__ unsigned bar_peek_acquire() {
    unsigned v;
    asm volatile("ld.acquire.gpu.global.u32 %0, [%1];"
                 : "=r"(v) : "l"(&g_bar) : "memory");
    return v;
}

// ---------------- fast gate math (MUFU-based, ~1e-7 rel err) ----------------
__device__ __forceinline__ float sigm_f(float x) {
    return __fdividef(1.f, 1.f + __expf(-x));
}
__device__ __forceinline__ float tanh_f(float x) {
    float e = __expf(2.f * x);
    return 1.f - __fdividef(2.f, e + 1.f);
}

// ---------------- tf32 helpers ----------------
__device__ __forceinline__ unsigned tf32cvt(float f) {
    unsigned r; asm("cvt.rna.tf32.f32 %0, %1;" : "=r"(r) : "f"(f)); return r;
}
__device__ __forceinline__ void mma_tf32(float* d, const unsigned* a, const unsigned* b) {
    asm("mma.sync.aligned.m16n8k8.row.col.f32.tf32.tf32.f32 "
        "{%0,%1,%2,%3}, {%4,%5,%6,%7}, {%8,%9}, {%0,%1,%2,%3};"
        : "+f"(d[0]), "+f"(d[1]), "+f"(d[2]), "+f"(d[3])
        : "r"(a[0]), "r"(a[1]), "r"(a[2]), "r"(a[3]), "r"(b[0]), "r"(b[1]));
}

// =====================================================================
// Kernel 1 (tf32 tensor cores): Wx = x[16384,512] @ W_w[2048,512]^T + W_b
// Block: 256 thr (8 warps), tile M128 x N128, K-chunk 32.
// Warp (wm 0..3, wn 0..1): m32 x n64 = 2 x 8 mma(m16n8k8) tiles per k-step.
// smem layout: row-major [row][k'] with k' interleaving (k, k+4) -> (2k%8...)
// so A frag (a0,a2) and B frag (b0,b1) are single LDS.64 each.
// k' within each 8-group: 0,4,1,5,2,6,3,7  (pair (t,t+4) -> (2t,2t+1)).
// =====================================================================
__global__ void __launch_bounds__(256) gemm_wx_tf32_kernel(
    const float* __restrict__ x, const float* __restrict__ Ww,
    const float* __restrict__ Wb)
{
    __shared__ __align__(16) unsigned As[128][36];
    __shared__ __align__(16) unsigned Bs[128][36];

    const int tid  = threadIdx.x;
    const int w    = tid >> 5;
    const int lane = tid & 31;
    const int g    = lane >> 2;    // fragment group row
    const int tig  = lane & 3;     // thread-in-group
    const int wm   = w >> 1;       // warp m index 0..3
    const int wn   = w & 1;        // warp n index 0..1
    const int m0   = blockIdx.y * 128;
    const int n0   = blockIdx.x * 128;

    const int lr = tid >> 1;       // copy row 0..127
    const int lh = tid & 1;        // copy k-half (16 floats)

    float acc[2][8][4];
    #pragma unroll
    for (int mt = 0; mt < 2; mt++)
        #pragma unroll
        for (int nt = 0; nt < 8; nt++)
            #pragma unroll
            for (int c = 0; c < 4; c++) acc[mt][nt][c] = 0.f;

    // preload chunk 0 into registers
    float4 ra[4], rb[4];
    {
        const float* pa = &x [(size_t)(m0 + lr) * 512 + lh * 16];
        const float* pb = &Ww[(size_t)(n0 + lr) * 512 + lh * 16];
        #pragma unroll
        for (int q = 0; q < 4; q++) {
            ra[q] = *(const float4*)(pa + 4 * q);
            rb[q] = *(const float4*)(pb + 4 * q);
        }
    }

    for (int chunk = 0; chunk < 16; chunk++) {
        __syncthreads();   // previous chunk's MMA reads done
        // cvt + interleaved store: f[16] covers k = lh*16 .. +15 of this chunk
        {
            const float* fa = (const float*)ra;
            const float* fb = (const float*)rb;
            #pragma unroll
            for (int g8 = 0; g8 < 2; g8++) {
                const int base = lh * 16 + g8 * 8;
                const float* f = fa + g8 * 8;
                uint4 v0 = make_uint4(tf32cvt(f[0]), tf32cvt(f[4]), tf32cvt(f[1]), tf32cvt(f[5]));
                uint4 v1 = make_uint4(tf32cvt(f[2]), tf32cvt(f[6]), tf32cvt(f[3]), tf32cvt(f[7]));
                *(uint4*)&As[lr][base]     = v0;
                *(uint4*)&As[lr][base + 4] = v1;
                const float* fw = fb + g8 * 8;
                uint4 w0 = make_uint4(tf32cvt(fw[0]), tf32cvt(fw[4]), tf32cvt(fw[1]), tf32cvt(fw[5]));
                uint4 w1 = make_uint4(tf32cvt(fw[2]), tf32cvt(fw[6]), tf32cvt(fw[3]), tf32cvt(fw[7]));
                *(uint4*)&Bs[lr][base]     = w0;
                *(uint4*)&Bs[lr][base + 4] = w1;
            }
        }
        __syncthreads();   // smem tiles ready

        // prefetch next chunk (overlaps MMA below)
        if (chunk < 15) {
            const int kc = (chunk + 1) * 32;
            const float* pa = &x [(size_t)(m0 + lr) * 512 + kc + lh * 16];
            const float* pb = &Ww[(size_t)(n0 + lr) * 512 + kc + lh * 16];
            #pragma unroll
            for (int q = 0; q < 4; q++) {
                ra[q] = *(const float4*)(pa + 4 * q);
                rb[q] = *(const float4*)(pb + 4 * q);
            }
        }

        // 4 k-steps of m16n8k8
        #pragma unroll
        for (int s = 0; s < 4; s++) {
            const int koff = 8 * s + 2 * tig;
            unsigned afrag[2][4];
            #pragma unroll
            for (int mt = 0; mt < 2; mt++) {
                const int rowA = wm * 32 + mt * 16 + g;
                uint2 p1 = *(const uint2*)&As[rowA][koff];
                uint2 p2 = *(const uint2*)&As[rowA + 8][koff];
                afrag[mt][0] = p1.x; afrag[mt][1] = p2.x;
                afrag[mt][2] = p1.y; afrag[mt][3] = p2.y;
            }
            #pragma unroll
            for (int nt = 0; nt < 8; nt++) {
                const int rowB = wn * 64 + nt * 8 + g;
                uint2 bp = *(const uint2*)&Bs[rowB][koff];
                unsigned bfrag[2] = { bp.x, bp.y };
                mma_tf32(acc[0][nt], afrag[0], bfrag);
                mma_tf32(acc[1][nt], afrag[1], bfrag);
            }
        }
    }

    // epilogue: add bias, write g_wx
    #pragma unroll
    for (int nt = 0; nt < 8; nt++) {
        const int colD = n0 + wn * 64 + nt * 8 + 2 * tig;
        const float2 wb2 = *(const float2*)&Wb[colD];
        #pragma unroll
        for (int mt = 0; mt < 2; mt++) {
            const int rowD = m0 + wm * 32 + mt * 16 + g;
            float2 lo = make_float2(acc[mt][nt][0] + wb2.x, acc[mt][nt][1] + wb2.y);
            float2 hi = make_float2(acc[mt][nt][2] + wb2.x, acc[mt][nt][3] + wb2.y);
            *(float2*)&g_wx[(size_t)rowD * FOURH + colD]       = lo;
            *(float2*)&g_wx[(size_t)(rowD + 8) * FOURH + colD] = hi;
        }
    }
}

// =====================================================================
// Kernel 2: persistent recurrent sLSTM — R6 VERBATIM (best measured).
// 128 blocks x 512 threads; warp w: gate g = w>>2, batch-pair bp = w&3.
// =====================================================================
__global__ void __launch_bounds__(512) lstm_rec_kernel(
    const float* __restrict__ Uw, const float* __restrict__ Ub,
    const float* __restrict__ alpha, float* __restrict__ out)
{
    __shared__ __align__(16) float h_s[Bb][Hh];   // 16 KB staged hidden state
    __shared__ float z_s[16][32];                 // per-warp reduced dots

    const int tid  = threadIdx.x;
    const int w    = tid >> 5;
    const int lane = tid & 31;
    const int g    = w >> 2;       // gate
    const int bp   = w & 3;        // batch pair (batches 2bp, 2bp+1)
    const int blk  = blockIdx.x;
    const int j0   = blk * 4;

    ulonglong2 u[4][4];
    #pragma unroll
    for (int r = 0; r < 4; r++)
        #pragma unroll
        for (int q = 0; q < 4; q++)
            u[r][q] = *(const ulonglong2*)&Uw[(size_t)(g * Hh + j0 + r) * Hh + 128 * q + 4 * lane];

    const int bb = lane & 7;
    const int jl = lane >> 3;
    float c_st = 0.f, alpha_r = 0.f;
    float ub_r[4] = {0.f, 0.f, 0.f, 0.f};
    if (w == 0) {
        #pragma unroll
        for (int gg = 0; gg < 4; gg++) ub_r[gg] = Ub[gg * Hh + j0 + jl];
        alpha_r = alpha[j0 + jl];
    }

    if (w == 0) {
        g_h[0][blk * 32 + lane] = 0.f;
        __syncwarp();
        if (lane == 0) bar_arrive_release();
    }
    __syncthreads();

    unsigned target = GRID_R;
    for (int t = 0; t < Tt; ++t) {
        float wx[4];
        if (w == 0) {
            const float* wp = &g_wx[((size_t)bb * Tt + t) * FOURH + j0 + jl];
            #pragma unroll
            for (int gg = 0; gg < 4; gg++) wx[gg] = __ldg(wp + gg * Hh);
        }

        if (tid == 0) {
            int spins = 0;
            while (bar_peek_acquire() < target) {
                if (++spins > 64) { __nanosleep(64); }
            }
        }
        __syncthreads();

        {
            const float4* src = (const float4*)g_h[t & 1];
            float4* dst = (float4*)&h_s[0][0];
            dst[tid]       = __ldcg(&src[tid]);
            dst[tid + 512] = __ldcg(&src[tid + 512]);
        }
        __syncthreads();

        u64 acc[4][2];
        #pragma unroll
        for (int r = 0; r < 4; r++) { acc[r][0] = 0ull; acc[r][1] = 0ull; }
        const int b0 = 2 * bp;
        #pragma unroll
        for (int bi = 0; bi < 2; bi++) {
            #pragma unroll
            for (int q = 0; q < 4; q++) {
                ulonglong2 h2 = *(const ulonglong2*)&h_s[b0 + bi][128 * q + 4 * lane];
                #pragma unroll
                for (int r = 0; r < 4; r++) {
                    fma2(acc[r][bi], u[r][q].x, h2.x);
                    fma2(acc[r][bi], u[r][q].y, h2.y);
                }
            }
        }

        float v[8];
        #pragma unroll
        for (int r = 0; r < 4; r++)
            #pragma unroll
            for (int bi = 0; bi < 2; bi++) {
                float lo, hi; unpack2(acc[r][bi], lo, hi);
                v[2 * r + bi] = lo + hi;
            }

        {
            const bool up16 = (lane & 16) != 0;
            #pragma unroll
            for (int i = 0; i < 4; i++) {
                float a = v[i], bv = v[i + 4];
                float mine = up16 ? bv : a, oth = up16 ? a : bv;
                v[i] = mine + __shfl_xor_sync(0xffffffffu, oth, 16);
            }
            const bool up8 = (lane & 8) != 0;
            #pragma unroll
            for (int i = 0; i < 2; i++) {
                float a = v[i], bv = v[i + 2];
                float mine = up8 ? bv : a, oth = up8 ? a : bv;
                v[i] = mine + __shfl_xor_sync(0xffffffffu, oth, 8);
            }
            const bool up4 = (lane & 4) != 0;
            {
                float a = v[0], bv = v[1];
                float mine = up4 ? bv : a, oth = up4 ? a : bv;
                v[0] = mine + __shfl_xor_sync(0xffffffffu, oth, 4);
            }
            v[0] += __shfl_xor_sync(0xffffffffu, v[0], 2);
            v[0] += __shfl_xor_sync(0xffffffffu, v[0], 1);
        }
        z_s[w][lane] = v[0];
        __syncthreads();

        if (w == 0) {
            float z[4];
            #pragma unroll
            for (int gg = 0; gg < 4; gg++) {
                int wsrc = gg * 4 + (bb >> 1);
                int lsrc = (2 * jl + (bb & 1)) * 4 + (bb >> 1);
                z[gg] = z_s[wsrc][lsrc] + wx[gg] + ub_r[gg];
            }
            float ig = sigm_f(z[0]), fg = sigm_f(z[1]), og = sigm_f(z[2]);
            float gg = tanh_f(z[3]);
            c_st = alpha_r * (fg * c_st + ig * gg);
            float hv = og * tanh_f(c_st);

            g_h[(t + 1) & 1][bb * Hh + j0 + jl] = hv;
            __syncwarp();
            if (lane == 0) bar_arrive_release();

            out[((size_t)bb * Tt + t) * Hh + j0 + jl] = hv;
            if (t == Tt - 1) {
                out[(size_t)Bb * Tt * Hh + bb * Hh + j0 + jl] = hv;
                out[(size_t)Bb * Tt * Hh + (size_t)Bb * Hh + bb * Hh + j0 + jl] = c_st;
            }
        }
        target += GRID_R;
    }

    if (tid == 0) {
        unsigned old = atomicAdd(&g_bar, 1u);
        if (old == (unsigned)(GRID_R * (Tt + 2) - 1))
            atomicExch(&g_bar, 0u);
    }
}

// =====================================================================
extern "C" void kernel_launch(void* const* d_in, const int* in_sizes, int n_in,
                              void* d_out, int out_size)
{
    const float* x     = (const float*)d_in[0];
    const float* Ww    = (const float*)d_in[1];
    const float* Wb    = (const float*)d_in[2];
    const float* Uw    = (const float*)d_in[3];
    const float* Ub    = (const float*)d_in[4];
    const float* alpha = (const float*)d_in[5];
    float* out = (float*)d_out;

    dim3 ggrid(FOURH / 128, (Bb * Tt) / 128);   // 16 x 128
    gemm_wx_tf32_kernel<<<ggrid, 256>>>(x, Ww, Wb);
    lstm_rec_kernel<<<GRID_R, 512>>>(Uw, Ub, alpha, out);
}

// round 11
// speedup vs baseline: 1.2774x; 1.1050x over previous
#include <cuda_runtime.h>
#include <cstddef>

#define Bb 8
#define Tt 2048
#define Dd 512
#define Hh 512
#define FOURH 2048
#define GRID_R 128
#define DOM_BLKS 32          // blocks per sync domain (2 batches per domain)

typedef unsigned long long u64;

// ---------------- scratch (static device globals: allocation-free) ----------------
__device__ float g_wx[(size_t)Bb * Tt * FOURH];   // 128 MiB: precomputed x @ W^T + b
__device__ float g_h[2][Bb * Hh];                 // double-buffered hidden state
__device__ unsigned g_cnt4[4 * 32];               // 4 per-domain counters, 128B apart

// ---------------- packed f32x2 helpers (b64 regs via "l" constraint) ----------------
__device__ __forceinline__ void fma2(u64 &acc, u64 a, u64 b) {
    asm("fma.rn.f32x2 %0, %1, %2, %0;" : "+l"(acc) : "l"(a), "l"(b));
}
__device__ __forceinline__ void unpack2(u64 v, float &lo, float &hi) {
    asm("mov.b64 {%0, %1}, %2;" : "=f"(lo), "=f"(hi) : "l"(v));
}

// ---------------- scoped sync primitives ----------------
__device__ __forceinline__ void cnt_arrive_release(unsigned* p) {
    asm volatile("red.release.gpu.global.add.u32 [%0], %1;"
                 :: "l"(p), "r"(1u) : "memory");
}
__device__ __forceinline__ unsigned ld_acquire(const unsigned* p) {
    unsigned v;
    asm volatile("ld.acquire.gpu.global.u32 %0, [%1];"
                 : "=r"(v) : "l"(p) : "memory");
    return v;
}

// ---------------- fast gate math (MUFU-based) ----------------
__device__ __forceinline__ float sigm_f(float x) {
    return __fdividef(1.f, 1.f + __expf(-x));
}
__device__ __forceinline__ float tanh_f(float x) {
    float e = __expf(2.f * x);
    return 1.f - __fdividef(2.f, e + 1.f);
}

// ---------------- tf32 helpers ----------------
__device__ __forceinline__ unsigned tf32cvt(float f) {
    unsigned r; asm("cvt.rna.tf32.f32 %0, %1;" : "=r"(r) : "f"(f)); return r;
}
__device__ __forceinline__ void mma_tf32(float* d, const unsigned* a, const unsigned* b) {
    asm("mma.sync.aligned.m16n8k8.row.col.f32.tf32.tf32.f32 "
        "{%0,%1,%2,%3}, {%4,%5,%6,%7}, {%8,%9}, {%0,%1,%2,%3};"
        : "+f"(d[0]), "+f"(d[1]), "+f"(d[2]), "+f"(d[3])
        : "r"(a[0]), "r"(a[1]), "r"(a[2]), "r"(a[3]), "r"(b[0]), "r"(b[1]));
}

// =====================================================================
// Kernel 1 (tf32 tensor cores): Wx = x @ W_w^T + W_b   (proven in R9)
// =====================================================================
__global__ void __launch_bounds__(256) gemm_wx_tf32_kernel(
    const float* __restrict__ x, const float* __restrict__ Ww,
    const float* __restrict__ Wb)
{
    __shared__ __align__(16) unsigned As[128][36];
    __shared__ __align__(16) unsigned Bs[128][36];

    const int tid  = threadIdx.x;
    const int w    = tid >> 5;
    const int lane = tid & 31;
    const int g    = lane >> 2;
    const int tig  = lane & 3;
    const int wm   = w >> 1;
    const int wn   = w & 1;
    const int m0   = blockIdx.y * 128;
    const int n0   = blockIdx.x * 128;

    const int lr = tid >> 1;
    const int lh = tid & 1;

    float acc[2][8][4];
    #pragma unroll
    for (int mt = 0; mt < 2; mt++)
        #pragma unroll
        for (int nt = 0; nt < 8; nt++)
            #pragma unroll
            for (int c = 0; c < 4; c++) acc[mt][nt][c] = 0.f;

    float4 ra[4], rb[4];
    {
        const float* pa = &x [(size_t)(m0 + lr) * 512 + lh * 16];
        const float* pb = &Ww[(size_t)(n0 + lr) * 512 + lh * 16];
        #pragma unroll
        for (int q = 0; q < 4; q++) {
            ra[q] = *(const float4*)(pa + 4 * q);
            rb[q] = *(const float4*)(pb + 4 * q);
        }
    }

    for (int chunk = 0; chunk < 16; chunk++) {
        __syncthreads();
        {
            const float* fa = (const float*)ra;
            const float* fb = (const float*)rb;
            #pragma unroll
            for (int g8 = 0; g8 < 2; g8++) {
                const int base = lh * 16 + g8 * 8;
                const float* f = fa + g8 * 8;
                uint4 v0 = make_uint4(tf32cvt(f[0]), tf32cvt(f[4]), tf32cvt(f[1]), tf32cvt(f[5]));
                uint4 v1 = make_uint4(tf32cvt(f[2]), tf32cvt(f[6]), tf32cvt(f[3]), tf32cvt(f[7]));
                *(uint4*)&As[lr][base]     = v0;
                *(uint4*)&As[lr][base + 4] = v1;
                const float* fw = fb + g8 * 8;
                uint4 w0 = make_uint4(tf32cvt(fw[0]), tf32cvt(fw[4]), tf32cvt(fw[1]), tf32cvt(fw[5]));
                uint4 w1 = make_uint4(tf32cvt(fw[2]), tf32cvt(fw[6]), tf32cvt(fw[3]), tf32cvt(fw[7]));
                *(uint4*)&Bs[lr][base]     = w0;
                *(uint4*)&Bs[lr][base + 4] = w1;
            }
        }
        __syncthreads();

        if (chunk < 15) {
            const int kc = (chunk + 1) * 32;
            const float* pa = &x [(size_t)(m0 + lr) * 512 + kc + lh * 16];
            const float* pb = &Ww[(size_t)(n0 + lr) * 512 + kc + lh * 16];
            #pragma unroll
            for (int q = 0; q < 4; q++) {
                ra[q] = *(const float4*)(pa + 4 * q);
                rb[q] = *(const float4*)(pb + 4 * q);
            }
        }

        #pragma unroll
        for (int s = 0; s < 4; s++) {
            const int koff = 8 * s + 2 * tig;
            unsigned afrag[2][4];
            #pragma unroll
            for (int mt = 0; mt < 2; mt++) {
                const int rowA = wm * 32 + mt * 16 + g;
                uint2 p1 = *(const uint2*)&As[rowA][koff];
                uint2 p2 = *(const uint2*)&As[rowA + 8][koff];
                afrag[mt][0] = p1.x; afrag[mt][1] = p2.x;
                afrag[mt][2] = p1.y; afrag[mt][3] = p2.y;
            }
            #pragma unroll
            for (int nt = 0; nt < 8; nt++) {
                const int rowB = wn * 64 + nt * 8 + g;
                uint2 bp = *(const uint2*)&Bs[rowB][koff];
                unsigned bfrag[2] = { bp.x, bp.y };
                mma_tf32(acc[0][nt], afrag[0], bfrag);
                mma_tf32(acc[1][nt], afrag[1], bfrag);
            }
        }
    }

    #pragma unroll
    for (int nt = 0; nt < 8; nt++) {
        const int colD = n0 + wn * 64 + nt * 8 + 2 * tig;
        const float2 wb2 = *(const float2*)&Wb[colD];
        #pragma unroll
        for (int mt = 0; mt < 2; mt++) {
            const int rowD = m0 + wm * 32 + mt * 16 + g;
            float2 lo = make_float2(acc[mt][nt][0] + wb2.x, acc[mt][nt][1] + wb2.y);
            float2 hi = make_float2(acc[mt][nt][2] + wb2.x, acc[mt][nt][3] + wb2.y);
            *(float2*)&g_wx[(size_t)rowD * FOURH + colD]       = lo;
            *(float2*)&g_wx[(size_t)(rowD + 8) * FOURH + colD] = hi;
        }
    }
}

// =====================================================================
// Kernel 2: persistent recurrent sLSTM, 4 INDEPENDENT sync domains.
// Domain d = blk>>5 owns batches {2d, 2d+1}; 32 blocks per domain.
// Block (d, s=blk&31) owns 16 hidden units j0 = s*16 .. +15.
// Warp w = uq*4 + g (uq=w>>2, g=w&3): gate g, units j0+4uq..+3, 2 batches.
// Finalize: warp 0, lane -> (unit u_l=lane>>1, batch bi=lane&1).
// =====================================================================
__global__ void __launch_bounds__(512) lstm_rec_kernel(
    const float* __restrict__ Uw, const float* __restrict__ Ub,
    const float* __restrict__ alpha, float* __restrict__ out)
{
    __shared__ __align__(16) float h_s[2][Hh];    // 4 KB: this domain's 2 h rows
    __shared__ float z_s[16][10];                 // padded: conflict-free finalize

    const int tid  = threadIdx.x;
    const int w    = tid >> 5;
    const int lane = tid & 31;
    const int uq   = w >> 2;        // unit quad 0..3
    const int g    = w & 3;         // gate
    const int blk  = blockIdx.x;
    const int dom  = blk >> 5;      // sync domain 0..3 (batches 2dom, 2dom+1)
    const int j0   = (blk & 31) * 16;
    const int B0   = 2 * dom;       // first batch of domain

    // U_w register-resident: rows (g, j0+4uq+r), lane cols 4*lane + 128*q
    ulonglong2 u[4][4];
    #pragma unroll
    for (int r = 0; r < 4; r++)
        #pragma unroll
        for (int q = 0; q < 4; q++)
            u[r][q] = *(const ulonglong2*)
                &Uw[(size_t)(g * Hh + j0 + 4 * uq + r) * Hh + 128 * q + 4 * lane];

    // finalize-warp per-lane constants: unit u_l = lane>>1, batch bi = lane&1
    const int u_l = lane >> 1;
    const int bi0 = lane & 1;
    const int Bf  = B0 + bi0;       // this lane's batch
    float c_st = 0.f, alpha_r = 0.f;
    float ub_r[4] = {0.f, 0.f, 0.f, 0.f};
    if (w == 0) {
        #pragma unroll
        for (int gg = 0; gg < 4; gg++) ub_r[gg] = Ub[gg * Hh + j0 + u_l];
        alpha_r = alpha[j0 + u_l];
    }

    unsigned* const my_cnt = &g_cnt4[dom * 32];

    // publish h0 = 0: warp 0 zeroes this block's 32 floats (16 units x 2 batches)
    if (w == 0) {
        g_h[0][Bf * Hh + j0 + u_l] = 0.f;
        __syncwarp();
        if (lane == 0) cnt_arrive_release(my_cnt);
    }
    __syncthreads();

    for (int t = 0; t < Tt; ++t) {
        // prefetch Wx_t for finalize lanes (independent of h)
        float wx[4];
        if (w == 0) {
            const float* wp = &g_wx[((size_t)Bf * Tt + t) * FOURH + j0 + u_l];
            #pragma unroll
            for (int gg = 0; gg < 4; gg++) wx[gg] = __ldg(wp + gg * Hh);
        }

        // ---- domain barrier: all 32 blocks of this domain published h_t
        if (tid == 0) {
            const unsigned tgt = (unsigned)DOM_BLKS * (unsigned)(t + 1);
            int spins = 0;
            while (ld_acquire(my_cnt) < tgt) {
                if (++spins > 64) __nanosleep(64);
            }
        }
        __syncthreads();

        // ---- stage this domain's 2 h rows (4 KB, contiguous; L2-only loads)
        if (tid < 256) {
            const float4* src = (const float4*)&g_h[t & 1][B0 * Hh];
            ((float4*)&h_s[0][0])[tid] = __ldcg(&src[tid]);
        }
        __syncthreads();

        // ---- dots: 4 rows x 2 batches over full 512 cols (from smem)
        u64 acc[4][2];
        #pragma unroll
        for (int r = 0; r < 4; r++) { acc[r][0] = 0ull; acc[r][1] = 0ull; }
        #pragma unroll
        for (int b2 = 0; b2 < 2; b2++) {
            #pragma unroll
            for (int q = 0; q < 4; q++) {
                ulonglong2 h2 = *(const ulonglong2*)&h_s[b2][128 * q + 4 * lane];
                #pragma unroll
                for (int r = 0; r < 4; r++) {
                    fma2(acc[r][b2], u[r][q].x, h2.x);
                    fma2(acc[r][b2], u[r][q].y, h2.y);
                }
            }
        }

        // collapse pair halves -> v[m], m = 2r + bi
        float v[8];
        #pragma unroll
        for (int r = 0; r < 4; r++)
            #pragma unroll
            for (int b2 = 0; b2 < 2; b2++) {
                float lo, hi; unpack2(acc[r][b2], lo, hi);
                v[2 * r + b2] = lo + hi;
            }

        // 9-shfl butterfly: lane L ends with total for m = (L>>2)&7
        {
            const bool up16 = (lane & 16) != 0;
            #pragma unroll
            for (int i = 0; i < 4; i++) {
                float a = v[i], bv = v[i + 4];
                float mine = up16 ? bv : a, oth = up16 ? a : bv;
                v[i] = mine + __shfl_xor_sync(0xffffffffu, oth, 16);
            }
            const bool up8 = (lane & 8) != 0;
            #pragma unroll
            for (int i = 0; i < 2; i++) {
                float a = v[i], bv = v[i + 2];
                float mine = up8 ? bv : a, oth = up8 ? a : bv;
                v[i] = mine + __shfl_xor_sync(0xffffffffu, oth, 8);
            }
            const bool up4 = (lane & 4) != 0;
            {
                float a = v[0], bv = v[1];
                float mine = up4 ? bv : a, oth = up4 ? a : bv;
                v[0] = mine + __shfl_xor_sync(0xffffffffu, oth, 4);
            }
            v[0] += __shfl_xor_sync(0xffffffffu, v[0], 2);
            v[0] += __shfl_xor_sync(0xffffffffu, v[0], 1);
        }
        if ((lane & 3) == 0) z_s[w][lane >> 2] = v[0];
        __syncthreads();

        // ---- finalize (warp 0): lane = (unit u_l, batch bi0)
        if (w == 0) {
            const int mi = 2 * (u_l & 3) + bi0;          // value index within source warp
            const int wq = (u_l >> 2) * 4;               // source warp base (unit quad)
            float z[4];
            #pragma unroll
            for (int gg = 0; gg < 4; gg++)
                z[gg] = z_s[wq + gg][mi] + wx[gg] + ub_r[gg];

            float ig = sigm_f(z[0]), fg = sigm_f(z[1]), og = sigm_f(z[2]);
            float gv = tanh_f(z[3]);
            c_st = alpha_r * (fg * c_st + ig * gv);
            float hv = og * tanh_f(c_st);

            g_h[(t + 1) & 1][Bf * Hh + j0 + u_l] = hv;
            __syncwarp();
            if (lane == 0) cnt_arrive_release(my_cnt);

            // off-critical-path stores
            out[((size_t)Bf * Tt + t) * Hh + j0 + u_l] = hv;
            if (t == Tt - 1) {
                out[(size_t)Bb * Tt * Hh + Bf * Hh + j0 + u_l] = hv;                     // final h
                out[(size_t)Bb * Tt * Hh + (size_t)Bb * Hh + Bf * Hh + j0 + u_l] = c_st; // final c
            }
        }
    }

    // domain's slice-0 block resets its counter once all arrivals landed
    if ((blk & 31) == 0 && tid == 0) {
        const unsigned fin = (unsigned)DOM_BLKS * (unsigned)(Tt + 1);
        int spins = 0;
        while (ld_acquire(my_cnt) < fin) {
            if (++spins > 64) __nanosleep(128);
        }
        *my_cnt = 0u;
    }
}

// =====================================================================
extern "C" void kernel_launch(void* const* d_in, const int* in_sizes, int n_in,
                              void* d_out, int out_size)
{
    const float* x     = (const float*)d_in[0];
    const float* Ww    = (const float*)d_in[1];
    const float* Wb    = (const float*)d_in[2];
    const float* Uw    = (const float*)d_in[3];
    const float* Ub    = (const float*)d_in[4];
    const float* alpha = (const float*)d_in[5];
    float* out = (float*)d_out;

    dim3 ggrid(FOURH / 128, (Bb * Tt) / 128);   // 16 x 128
    gemm_wx_tf32_kernel<<<ggrid, 256>>>(x, Ww, Wb);
    lstm_rec_kernel<<<GRID_R, 512>>>(Uw, Ub, alpha, out);
}

// round 12
// speedup vs baseline: 1.3438x; 1.0520x over previous
#include <cuda_runtime.h>
#include <cstddef>

#define Bb 8
#define Tt 2048
#define Dd 512
#define Hh 512
#define FOURH 2048
#define GRID_R 128
#define DOM_BLKS 32          // blocks per sync domain (2 batches per domain)

typedef unsigned long long u64;

// ---------------- scratch (static device globals: allocation-free) ----------------
__device__ float g_wx[(size_t)Bb * Tt * FOURH];   // 128 MiB: precomputed x @ W^T + b
__device__ float g_h[2][Bb * Hh];                 // double-buffered hidden state
__device__ unsigned g_cnt4[4 * 32];               // 4 per-domain counters, 128B apart

// ---------------- packed f32x2 helpers (b64 regs via "l" constraint) ----------------
__device__ __forceinline__ void fma2(u64 &acc, u64 a, u64 b) {
    asm("fma.rn.f32x2 %0, %1, %2, %0;" : "+l"(acc) : "l"(a), "l"(b));
}
__device__ __forceinline__ void unpack2(u64 v, float &lo, float &hi) {
    asm("mov.b64 {%0, %1}, %2;" : "=f"(lo), "=f"(hi) : "l"(v));
}

// ---------------- scoped sync primitives ----------------
__device__ __forceinline__ void cnt_arrive_release(unsigned* p) {
    asm volatile("red.release.gpu.global.add.u32 [%0], %1;"
                 :: "l"(p), "r"(1u) : "memory");
}
__device__ __forceinline__ unsigned ld_acquire(const unsigned* p) {
    unsigned v;
    asm volatile("ld.acquire.gpu.global.u32 %0, [%1];"
                 : "=r"(v) : "l"(p) : "memory");
    return v;
}

// ---------------- fast gate math (MUFU-based) ----------------
__device__ __forceinline__ float sigm_f(float x) {
    return __fdividef(1.f, 1.f + __expf(-x));
}
__device__ __forceinline__ float tanh_f(float x) {
    float e = __expf(2.f * x);
    return 1.f - __fdividef(2.f, e + 1.f);
}

// ---------------- tf32 helpers ----------------
__device__ __forceinline__ unsigned tf32cvt(float f) {
    unsigned r; asm("cvt.rna.tf32.f32 %0, %1;" : "=r"(r) : "f"(f)); return r;
}
__device__ __forceinline__ void mma_tf32(float* d, const unsigned* a, const unsigned* b) {
    asm("mma.sync.aligned.m16n8k8.row.col.f32.tf32.tf32.f32 "
        "{%0,%1,%2,%3}, {%4,%5,%6,%7}, {%8,%9}, {%0,%1,%2,%3};"
        : "+f"(d[0]), "+f"(d[1]), "+f"(d[2]), "+f"(d[3])
        : "r"(a[0]), "r"(a[1]), "r"(a[2]), "r"(a[3]), "r"(b[0]), "r"(b[1]));
}

// =====================================================================
// Kernel 1 (tf32 tensor cores): Wx = x @ W_w^T + W_b   (R9 verbatim)
// =====================================================================
__global__ void __launch_bounds__(256) gemm_wx_tf32_kernel(
    const float* __restrict__ x, const float* __restrict__ Ww,
    const float* __restrict__ Wb)
{
    __shared__ __align__(16) unsigned As[128][36];
    __shared__ __align__(16) unsigned Bs[128][36];

    const int tid  = threadIdx.x;
    const int w    = tid >> 5;
    const int lane = tid & 31;
    const int g    = lane >> 2;
    const int tig  = lane & 3;
    const int wm   = w >> 1;
    const int wn   = w & 1;
    const int m0   = blockIdx.y * 128;
    const int n0   = blockIdx.x * 128;

    const int lr = tid >> 1;
    const int lh = tid & 1;

    float acc[2][8][4];
    #pragma unroll
    for (int mt = 0; mt < 2; mt++)
        #pragma unroll
        for (int nt = 0; nt < 8; nt++)
            #pragma unroll
            for (int c = 0; c < 4; c++) acc[mt][nt][c] = 0.f;

    float4 ra[4], rb[4];
    {
        const float* pa = &x [(size_t)(m0 + lr) * 512 + lh * 16];
        const float* pb = &Ww[(size_t)(n0 + lr) * 512 + lh * 16];
        #pragma unroll
        for (int q = 0; q < 4; q++) {
            ra[q] = *(const float4*)(pa + 4 * q);
            rb[q] = *(const float4*)(pb + 4 * q);
        }
    }

    for (int chunk = 0; chunk < 16; chunk++) {
        __syncthreads();
        {
            const float* fa = (const float*)ra;
            const float* fb = (const float*)rb;
            #pragma unroll
            for (int g8 = 0; g8 < 2; g8++) {
                const int base = lh * 16 + g8 * 8;
                const float* f = fa + g8 * 8;
                uint4 v0 = make_uint4(tf32cvt(f[0]), tf32cvt(f[4]), tf32cvt(f[1]), tf32cvt(f[5]));
                uint4 v1 = make_uint4(tf32cvt(f[2]), tf32cvt(f[6]), tf32cvt(f[3]), tf32cvt(f[7]));
                *(uint4*)&As[lr][base]     = v0;
                *(uint4*)&As[lr][base + 4] = v1;
                const float* fw = fb + g8 * 8;
                uint4 w0 = make_uint4(tf32cvt(fw[0]), tf32cvt(fw[4]), tf32cvt(fw[1]), tf32cvt(fw[5]));
                uint4 w1 = make_uint4(tf32cvt(fw[2]), tf32cvt(fw[6]), tf32cvt(fw[3]), tf32cvt(fw[7]));
                *(uint4*)&Bs[lr][base]     = w0;
                *(uint4*)&Bs[lr][base + 4] = w1;
            }
        }
        __syncthreads();

        if (chunk < 15) {
            const int kc = (chunk + 1) * 32;
            const float* pa = &x [(size_t)(m0 + lr) * 512 + kc + lh * 16];
            const float* pb = &Ww[(size_t)(n0 + lr) * 512 + kc + lh * 16];
            #pragma unroll
            for (int q = 0; q < 4; q++) {
                ra[q] = *(const float4*)(pa + 4 * q);
                rb[q] = *(const float4*)(pb + 4 * q);
            }
        }

        #pragma unroll
        for (int s = 0; s < 4; s++) {
            const int koff = 8 * s + 2 * tig;
            unsigned afrag[2][4];
            #pragma unroll
            for (int mt = 0; mt < 2; mt++) {
                const int rowA = wm * 32 + mt * 16 + g;
                uint2 p1 = *(const uint2*)&As[rowA][koff];
                uint2 p2 = *(const uint2*)&As[rowA + 8][koff];
                afrag[mt][0] = p1.x; afrag[mt][1] = p2.x;
                afrag[mt][2] = p1.y; afrag[mt][3] = p2.y;
            }
            #pragma unroll
            for (int nt = 0; nt < 8; nt++) {
                const int rowB = wn * 64 + nt * 8 + g;
                uint2 bp = *(const uint2*)&Bs[rowB][koff];
                unsigned bfrag[2] = { bp.x, bp.y };
                mma_tf32(acc[0][nt], afrag[0], bfrag);
                mma_tf32(acc[1][nt], afrag[1], bfrag);
            }
        }
    }

    #pragma unroll
    for (int nt = 0; nt < 8; nt++) {
        const int colD = n0 + wn * 64 + nt * 8 + 2 * tig;
        const float2 wb2 = *(const float2*)&Wb[colD];
        #pragma unroll
        for (int mt = 0; mt < 2; mt++) {
            const int rowD = m0 + wm * 32 + mt * 16 + g;
            float2 lo = make_float2(acc[mt][nt][0] + wb2.x, acc[mt][nt][1] + wb2.y);
            float2 hi = make_float2(acc[mt][nt][2] + wb2.x, acc[mt][nt][3] + wb2.y);
            *(float2*)&g_wx[(size_t)rowD * FOURH + colD]       = lo;
            *(float2*)&g_wx[(size_t)(rowD + 8) * FOURH + colD] = hi;
        }
    }
}

// =====================================================================
// Kernel 2: persistent recurrent sLSTM, 4 sync domains, DISTRIBUTED
// finalize (no serial warp-0 tail, no z_s).
// Domain d = blk>>5 owns batches {2d, 2d+1}; 32 blocks/domain.
// Block owns 16 units j0 = (blk&31)*16.
// Warp w owns unit jg = j0 + w: ALL 4 gates x 2 batches (8 dots of 512).
// Lane slot m=(lane>>2)&7 -> gate g_l=m&3, batch-half bi_l=m>>2.
// After butterfly each lane activates its slot; lanes 0/16 hold c and
// publish h. One release-RED per block per step.
// =====================================================================
__global__ void __launch_bounds__(512) lstm_rec_kernel(
    const float* __restrict__ Uw, const float* __restrict__ Ub,
    const float* __restrict__ alpha, float* __restrict__ out)
{
    __shared__ __align__(16) float h_s[2][Hh];    // 4 KB: this domain's 2 h rows

    const int tid  = threadIdx.x;
    const int w    = tid >> 5;
    const int lane = tid & 31;
    const int blk  = blockIdx.x;
    const int dom  = blk >> 5;
    const int j0   = (blk & 31) * 16;
    const int B0   = 2 * dom;
    const int jg   = j0 + w;        // this warp's hidden unit

    // lane slot: m = (lane>>2)&7 -> gate, batch-half
    const int m    = (lane >> 2) & 7;
    const int g_l  = m & 3;
    const int bi_l = m >> 2;
    const int Bf   = B0 + bi_l;

    // U_w register-resident: rows (g, jg) g=0..3; lane cols 4*lane + 128*q
    ulonglong2 u[4][4];
    #pragma unroll
    for (int g = 0; g < 4; g++)
        #pragma unroll
        for (int q = 0; q < 4; q++)
            u[g][q] = *(const ulonglong2*)&Uw[(size_t)(g * Hh + jg) * Hh + 128 * q + 4 * lane];

    const float ub_r    = Ub[g_l * Hh + jg];
    const float alpha_r = alpha[jg];
    float c_st = 0.f;               // live in lanes 0 (batch B0) and 16 (B0+1)

    unsigned* const my_cnt = &g_cnt4[dom * 32];

    // publish h0 = 0: warp 0 zeroes this block's 32 floats (16 units x 2 batches)
    if (w == 0) {
        g_h[0][(B0 + (lane & 1)) * Hh + j0 + (lane >> 1)] = 0.f;
        __syncwarp();
        if (lane == 0) cnt_arrive_release(my_cnt);
    }
    __syncthreads();

    for (int t = 0; t < Tt; ++t) {
        // prefetch Wx_t for this lane's slot (independent of h; L1-cached)
        const float wx = __ldg(&g_wx[((size_t)Bf * Tt + t) * FOURH + g_l * Hh + jg]);

        // ---- domain barrier: all 32 blocks of this domain published h_t
        if (tid == 0) {
            const unsigned tgt = (unsigned)DOM_BLKS * (unsigned)(t + 1);
            int spins = 0;
            while (ld_acquire(my_cnt) < tgt) {
                if (++spins > 64) __nanosleep(64);
            }
        }
        __syncthreads();

        // ---- stage this domain's 2 h rows (4 KB; L2-only loads)
        if (tid < 256) {
            const float4* src = (const float4*)&g_h[t & 1][B0 * Hh];
            ((float4*)&h_s[0][0])[tid] = __ldcg(&src[tid]);
        }
        __syncthreads();

        // ---- dots: 4 gates x 2 batches over full 512 cols (from smem)
        u64 acc[4][2];
        #pragma unroll
        for (int g = 0; g < 4; g++) { acc[g][0] = 0ull; acc[g][1] = 0ull; }
        #pragma unroll
        for (int b2 = 0; b2 < 2; b2++) {
            #pragma unroll
            for (int q = 0; q < 4; q++) {
                ulonglong2 h2 = *(const ulonglong2*)&h_s[b2][128 * q + 4 * lane];
                #pragma unroll
                for (int g = 0; g < 4; g++) {
                    fma2(acc[g][b2], u[g][q].x, h2.x);
                    fma2(acc[g][b2], u[g][q].y, h2.y);
                }
            }
        }

        // collapse pair halves -> v[mm], mm = gate + 4*batchhalf
        float v[8];
        #pragma unroll
        for (int g = 0; g < 4; g++)
            #pragma unroll
            for (int b2 = 0; b2 < 2; b2++) {
                float lo, hi; unpack2(acc[g][b2], lo, hi);
                v[g + 4 * b2] = lo + hi;
            }

        // 9-shfl butterfly: lane L ends with total for mm = (L>>2)&7
        {
            const bool up16 = (lane & 16) != 0;
            #pragma unroll
            for (int i = 0; i < 4; i++) {
                float a = v[i], bv = v[i + 4];
                float mine = up16 ? bv : a, oth = up16 ? a : bv;
                v[i] = mine + __shfl_xor_sync(0xffffffffu, oth, 16);
            }
            const bool up8 = (lane & 8) != 0;
            #pragma unroll
            for (int i = 0; i < 2; i++) {
                float a = v[i], bv = v[i + 2];
                float mine = up8 ? bv : a, oth = up8 ? a : bv;
                v[i] = mine + __shfl_xor_sync(0xffffffffu, oth, 8);
            }
            const bool up4 = (lane & 4) != 0;
            {
                float a = v[0], bv = v[1];
                float mine = up4 ? bv : a, oth = up4 ? a : bv;
                v[0] = mine + __shfl_xor_sync(0xffffffffu, oth, 4);
            }
            v[0] += __shfl_xor_sync(0xffffffffu, v[0], 2);
            v[0] += __shfl_xor_sync(0xffffffffu, v[0], 1);
        }

        // parallel activations: each lane activates its own slot
        const float z = v[0] + wx + ub_r;
        const float a = (g_l == 3) ? tanh_f(z) : sigm_f(z);

        // gather i/f/o/g at lanes 0 (bi=0) and 16 (bi=1); update c; store h
        const float a_f = __shfl_down_sync(0xffffffffu, a, 4);
        const float a_o = __shfl_down_sync(0xffffffffu, a, 8);
        const float a_g = __shfl_down_sync(0xffffffffu, a, 12);
        float hv = 0.f;
        if ((lane & 15) == 0) {
            c_st = alpha_r * (a_f * c_st + a * a_g);
            hv = a_o * tanh_f(c_st);
            g_h[(t + 1) & 1][Bf * Hh + jg] = hv;
        }

        // ---- all warps' h stores done -> single release-RED per block
        __syncthreads();
        if (tid == 0) cnt_arrive_release(my_cnt);

        // off-critical-path stores (kernel-end fence covers visibility)
        if ((lane & 15) == 0) {
            out[((size_t)Bf * Tt + t) * Hh + jg] = hv;
            if (t == Tt - 1) {
                out[(size_t)Bb * Tt * Hh + Bf * Hh + jg] = hv;                      // final h
                out[(size_t)Bb * Tt * Hh + (size_t)Bb * Hh + Bf * Hh + jg] = c_st;  // final c
            }
        }
    }

    // domain's slice-0 block resets its counter once all arrivals landed
    if ((blk & 31) == 0 && tid == 0) {
        const unsigned fin = (unsigned)DOM_BLKS * (unsigned)(Tt + 1);
        int spins = 0;
        while (ld_acquire(my_cnt) < fin) {
            if (++spins > 64) __nanosleep(128);
        }
        *my_cnt = 0u;
    }
}

// =====================================================================
extern "C" void kernel_launch(void* const* d_in, const int* in_sizes, int n_in,
                              void* d_out, int out_size)
{
    const float* x     = (const float*)d_in[0];
    const float* Ww    = (const float*)d_in[1];
    const float* Wb    = (const float*)d_in[2];
    const float* Uw    = (const float*)d_in[3];
    const float* Ub    = (const float*)d_in[4];
    const float* alpha = (const float*)d_in[5];
    float* out = (float*)d_out;

    dim3 ggrid(FOURH / 128, (Bb * Tt) / 128);   // 16 x 128
    gemm_wx_tf32_kernel<<<ggrid, 256>>>(x, Ww, Wb);
    lstm_rec_kernel<<<GRID_R, 512>>>(Uw, Ub, alpha, out);
}